// round 8
// baseline (speedup 1.0000x reference)
#include <cuda_runtime.h>
#include <cstdint>

// ---------------- problem constants ----------------
#define NB   4
#define C64  64
#define CR   32
#define HLq  96
#define WLq  96
#define HSk  48
#define WSk  48
#define Pq   (HLq*WLq)     // 9216 queries
#define Lk   (HSk*WSk)     // 2304 keys
#define KQ   (CR*9)        // 288  (32 ch * 3x3 patch)

// ---------------- device scratch (static, allocation-free) ----------------
__device__ float g_mb   [(size_t)NB*CR*Pq];     // match_base [N,32,96,96]
__device__ float g_ref  [(size_t)NB*CR*Lk];     // ref        [N,32,48,48]
__device__ float g_base [(size_t)NB*C64*Lk];    // base       [N,64,48,48]
__device__ float g_baseT[(size_t)NB*Lk*C64];    // base^T     [N,2304,64]
__device__ float g_xq   [(size_t)NB*Pq*KQ];     // query patches [N,9216,288]
__device__ float g_wkT  [(size_t)NB*KQ*Lk];     // normalized key patches, transposed [N,288,2304]
__device__ float g_probs[(size_t)NB*Pq*Lk];     // scores -> probs -> (after stencil_h) G
__device__ float g_G    [(size_t)NB*Pq*Lk];     // intermediate T (w-pass stencil)

// ---------------- 1x1 conv + PReLU ----------------
template<int CO, int HW>
__device__ __forceinline__ void conv_body(const float* __restrict__ in,
                                          const float* __restrict__ w,
                                          const float* __restrict__ b,
                                          const float* __restrict__ a,
                                          float* __restrict__ out) {
    __shared__ float ws[CO*64];
    __shared__ float bs[CO];
    int tid = threadIdx.x;
    for (int i = tid; i < CO*64; i += 256) ws[i] = w[i];
    for (int i = tid; i < CO;    i += 256) bs[i] = b[i];
    __syncthreads();
    float alpha = __ldg(a);
    int n = blockIdx.y;
    int p = (blockIdx.x << 8) + tid;
    const float* inp = in + (size_t)n*64*HW + p;
    float acc[CO];
#pragma unroll
    for (int co = 0; co < CO; co++) acc[co] = bs[co];
    for (int ci = 0; ci < 64; ci++) {
        float x = inp[(size_t)ci*HW];
#pragma unroll
        for (int co = 0; co < CO; co++) acc[co] = fmaf(ws[co*64+ci], x, acc[co]);
    }
    float* op = out + (size_t)n*CO*HW + p;
#pragma unroll
    for (int co = 0; co < CO; co++) {
        float v = acc[co];
        op[(size_t)co*HW] = v >= 0.f ? v : alpha*v;
    }
}

__global__ __launch_bounds__(256) void k_conv_mb(const float* __restrict__ in,
    const float* __restrict__ w, const float* __restrict__ b, const float* __restrict__ a) {
    conv_body<CR, Pq>(in, w, b, a, g_mb);
}
__global__ __launch_bounds__(256) void k_conv_ref(const float* __restrict__ in,
    const float* __restrict__ w, const float* __restrict__ b, const float* __restrict__ a) {
    conv_body<CR, Lk>(in, w, b, a, g_ref);
}
__global__ __launch_bounds__(256) void k_conv_base(const float* __restrict__ in,
    const float* __restrict__ w, const float* __restrict__ b, const float* __restrict__ a) {
    conv_body<C64, Lk>(in, w, b, a, g_base);
}

// ---------------- build query patch matrix [N, P, 288] ----------------
__global__ __launch_bounds__(256) void k_build_xq() {
    size_t idx = (size_t)blockIdx.x * 256 + threadIdx.x;   // over NB*Pq*KQ (exact grid)
    int k = (int)(idx % KQ);
    size_t t = idx / KQ;
    int p = (int)(t % Pq);
    int n = (int)(t / Pq);
    int c = k / 9, tap = k % 9;
    int h = p / WLq + tap / 3 - 1;
    int w = p % WLq + tap % 3 - 1;
    float v = 0.f;
    if ((unsigned)h < HLq && (unsigned)w < WLq)
        v = g_mb[(((size_t)n*CR + c)*HLq + h)*WLq + w];
    g_xq[idx] = v;
}

// ---------------- build normalized key patches (transposed) [N, 288, L] ----------------
__global__ void k_build_wk() {   // blockDim = 288 (= 9 warps)
    int n = blockIdx.y, l = blockIdx.x;
    int t = threadIdx.x;             // 0..287 : k index c*9 + tap
    int c = t / 9, tap = t % 9;
    int h = l / WSk + tap / 3 - 1;
    int w = l % WSk + tap % 3 - 1;
    float v = 0.f;
    if ((unsigned)h < HSk && (unsigned)w < WSk)
        v = g_ref[(((size_t)n*CR + c)*HSk + h)*WSk + w];
    float s = v*v;
#pragma unroll
    for (int o = 16; o > 0; o >>= 1) s += __shfl_xor_sync(0xffffffffu, s, o);
    __shared__ float part[9];
    __shared__ float nrm;
    if ((t & 31) == 0) part[t >> 5] = s;
    __syncthreads();
    if (t == 0) {
        float tot = 0.f;
#pragma unroll
        for (int i = 0; i < 9; i++) tot += part[i];
        nrm = 1.f / (sqrtf(tot) + 1e-4f);
    }
    __syncthreads();
    g_wkT[((size_t)n*KQ + t)*Lk + l] = v * nrm;
}

// ---------------- transpose base -> [N, L, 64] ----------------
__global__ __launch_bounds__(256) void k_baseT() {
    int idx = (blockIdx.x << 8) + threadIdx.x;     // over NB*Lk*64 (exact)
    int c = idx & 63;
    int t = idx >> 6;
    int l = t % Lk;
    int n = t / Lk;
    g_baseT[idx] = g_base[((size_t)n*C64 + c)*Lk + l];
}

// ---------------- scores GEMM: g_probs = 10 * g_xq @ g_wkT  (per sample) ----------------
// M=9216, N=2304, K=288; 128x128 tile, BK=8, 256 thr, 8x8 microtile
__global__ __launch_bounds__(256) void k_sgemm_scores() {
    __shared__ float As[8][128];
    __shared__ float Bs[8][128];
    const int z = blockIdx.z;
    const float* A = g_xq  + (size_t)z*Pq*KQ;
    const float* B = g_wkT + (size_t)z*KQ*Lk;
    float* Cm      = g_probs + (size_t)z*Pq*Lk;
    const int bm = blockIdx.y << 7;
    const int bn = blockIdx.x << 7;
    const int tid  = threadIdx.x;
    const int arow = tid >> 1, acol = (tid & 1) << 2;
    const int brow = tid >> 5, bcol = (tid & 31) << 2;
    const int ty = tid >> 4,  tx = tid & 15;
    float acc[8][8];
#pragma unroll
    for (int i = 0; i < 8; i++)
#pragma unroll
        for (int j = 0; j < 8; j++) acc[i][j] = 0.f;
    const float* Aptr = A + (size_t)(bm + arow)*KQ + acol;
    const float* Bptr = B + (size_t)brow*Lk + bn + bcol;
    for (int k0 = 0; k0 < KQ; k0 += 8) {
        float4 av = *reinterpret_cast<const float4*>(Aptr + k0);
        float4 bv = *reinterpret_cast<const float4*>(Bptr + (size_t)k0*Lk);
        As[acol+0][arow] = av.x; As[acol+1][arow] = av.y;
        As[acol+2][arow] = av.z; As[acol+3][arow] = av.w;
        *reinterpret_cast<float4*>(&Bs[brow][bcol]) = bv;
        __syncthreads();
#pragma unroll
        for (int kk = 0; kk < 8; kk++) {
            float ar[8], br[8];
            *reinterpret_cast<float4*>(&ar[0]) = *reinterpret_cast<float4*>(&As[kk][ty<<3]);
            *reinterpret_cast<float4*>(&ar[4]) = *reinterpret_cast<float4*>(&As[kk][(ty<<3)+4]);
            *reinterpret_cast<float4*>(&br[0]) = *reinterpret_cast<float4*>(&Bs[kk][tx<<3]);
            *reinterpret_cast<float4*>(&br[4]) = *reinterpret_cast<float4*>(&Bs[kk][(tx<<3)+4]);
#pragma unroll
            for (int i = 0; i < 8; i++)
#pragma unroll
                for (int j = 0; j < 8; j++) acc[i][j] = fmaf(ar[i], br[j], acc[i][j]);
        }
        __syncthreads();
    }
#pragma unroll
    for (int i = 0; i < 8; i++) {
        size_t off = (size_t)(bm + (ty<<3) + i)*Lk + bn + (tx<<3);
        float4 o0, o1;
        o0.x = 10.f*acc[i][0]; o0.y = 10.f*acc[i][1]; o0.z = 10.f*acc[i][2]; o0.w = 10.f*acc[i][3];
        o1.x = 10.f*acc[i][4]; o1.y = 10.f*acc[i][5]; o1.z = 10.f*acc[i][6]; o1.w = 10.f*acc[i][7];
        *reinterpret_cast<float4*>(Cm + off)     = o0;
        *reinterpret_cast<float4*>(Cm + off + 4) = o1;
    }
}

// ---------------- softmax over L=2304 (in place), block per (p, n) ----------------
__global__ __launch_bounds__(256) void k_softmax() {
    int p = blockIdx.x, n = blockIdx.y;
    float* row = g_probs + ((size_t)n*Pq + p) * (size_t)Lk;
    int t = threadIdx.x;
    float v[9];
    float m = -1e30f;
#pragma unroll
    for (int i = 0; i < 9; i++) { v[i] = row[i*256 + t]; m = fmaxf(m, v[i]); }
    __shared__ float red[8];
    __shared__ float bval;
#pragma unroll
    for (int o = 16; o > 0; o >>= 1) m = fmaxf(m, __shfl_xor_sync(0xffffffffu, m, o));
    if ((t & 31) == 0) red[t >> 5] = m;
    __syncthreads();
    if (t == 0) {
        float x = red[0];
#pragma unroll
        for (int i = 1; i < 8; i++) x = fmaxf(x, red[i]);
        bval = x;
    }
    __syncthreads();
    float mm = bval;
    float s = 0.f;
#pragma unroll
    for (int i = 0; i < 9; i++) { v[i] = expf(v[i] - mm); s += v[i]; }
#pragma unroll
    for (int o = 16; o > 0; o >>= 1) s += __shfl_xor_sync(0xffffffffu, s, o);
    if ((t & 31) == 0) red[t >> 5] = s;
    __syncthreads();
    if (t == 0) {
        float x = 0.f;
#pragma unroll
        for (int i = 0; i < 8; i++) x += red[i];
        bval = x;
    }
    __syncthreads();
    float inv = 1.f / bval;
#pragma unroll
    for (int i = 0; i < 9; i++) row[i*256 + t] = v[i] * inv;
}

// ---------------- separable diagonal 9-point stencil ----------------
// G[p',lb] = sum_{dy,dx} probs[p' + 96dy + dx, lb + 48dy + dx] with per-axis bounds.
// w-pass: probs -> g_G ; h-pass: g_G -> probs (reused as G)
__global__ __launch_bounds__(256) void k_stencil_w() {
    int l = (blockIdx.x << 8) + threadIdx.x;
    int p = blockIdx.y, n = blockIdx.z;
    const float* r = g_probs + ((size_t)n*Pq + p) * (size_t)Lk;
    int wq = p % WLq;
    int wb = l % WSk;
    float s = r[l];
    if (wq > 0      && wb > 0)      s += r[(long)l - (Lk + 1)];
    if (wq < WLq-1  && wb < WSk-1)  s += r[(long)l + (Lk + 1)];
    g_G[((size_t)n*Pq + p)*(size_t)Lk + l] = s;
}
__global__ __launch_bounds__(256) void k_stencil_h() {
    int l = (blockIdx.x << 8) + threadIdx.x;
    int p = blockIdx.y, n = blockIdx.z;
    const float* r = g_G + ((size_t)n*Pq + p) * (size_t)Lk;
    int hq = p / WLq;
    int hb = l / WSk;
    const long D = (long)WLq * Lk + WSk;    // 96 rows + 48 cols
    float s = r[l];
    if (hq > 0     && hb > 0)      s += r[(long)l - D];
    if (hq < HLq-1 && hb < HSk-1)  s += r[(long)l + D];
    g_probs[((size_t)n*Pq + p)*(size_t)Lk + l] = s;
}

// ---------------- output GEMM: y = 0.25 * G @ baseT + input_l ----------------
// M=9216, N=64, K=2304; 128x64 tile, BK=16, 256 thr, 8x4 microtile, fused epilogue
__global__ __launch_bounds__(256) void k_sgemm_out(const float* __restrict__ inl,
                                                   float* __restrict__ out) {
    __shared__ float As[16][128];
    __shared__ float Bs[16][64];
    const int n = blockIdx.y;
    const float* A = g_probs + (size_t)n*Pq*Lk;     // G
    const float* B = g_baseT + (size_t)n*Lk*C64;
    const int bm = blockIdx.x << 7;
    const int tid  = threadIdx.x;
    const int arow = tid & 127, acol = (tid >> 7) << 3;   // 0 or 8
    const int brow = tid >> 4,  bcol = (tid & 15) << 2;
    const int ty = tid >> 4, tx = tid & 15;
    float acc[8][4];
#pragma unroll
    for (int i = 0; i < 8; i++)
#pragma unroll
        for (int j = 0; j < 4; j++) acc[i][j] = 0.f;
    const float* Aptr = A + (size_t)(bm + arow)*Lk + acol;
    const float* Bptr = B + (size_t)brow*C64 + bcol;
    for (int k0 = 0; k0 < Lk; k0 += 16) {
        float4 a0 = *reinterpret_cast<const float4*>(Aptr + k0);
        float4 a1 = *reinterpret_cast<const float4*>(Aptr + k0 + 4);
        float4 bv = *reinterpret_cast<const float4*>(Bptr + (size_t)k0*C64);
        As[acol+0][arow] = a0.x; As[acol+1][arow] = a0.y;
        As[acol+2][arow] = a0.z; As[acol+3][arow] = a0.w;
        As[acol+4][arow] = a1.x; As[acol+5][arow] = a1.y;
        As[acol+6][arow] = a1.z; As[acol+7][arow] = a1.w;
        *reinterpret_cast<float4*>(&Bs[brow][bcol]) = bv;
        __syncthreads();
#pragma unroll
        for (int kk = 0; kk < 16; kk++) {
            float ar[8], br[4];
            *reinterpret_cast<float4*>(&ar[0]) = *reinterpret_cast<float4*>(&As[kk][ty<<3]);
            *reinterpret_cast<float4*>(&ar[4]) = *reinterpret_cast<float4*>(&As[kk][(ty<<3)+4]);
            *reinterpret_cast<float4*>(&br[0]) = *reinterpret_cast<float4*>(&Bs[kk][tx<<2]);
#pragma unroll
            for (int i = 0; i < 8; i++)
#pragma unroll
                for (int j = 0; j < 4; j++) acc[i][j] = fmaf(ar[i], br[j], acc[i][j]);
        }
        __syncthreads();
    }
    // epilogue: out[n][c][p] = 0.25*acc + input_l[n][c][p] ; c = tx*4+j, p = bm+ty*8+i
#pragma unroll
    for (int j = 0; j < 4; j++) {
        int c = (tx << 2) + j;
        size_t off = ((size_t)n*C64 + c)*Pq + bm + (ty << 3);
        float4 r0 = *reinterpret_cast<const float4*>(inl + off);
        float4 r1 = *reinterpret_cast<const float4*>(inl + off + 4);
        float4 o0, o1;
        o0.x = 0.25f*acc[0][j] + r0.x; o0.y = 0.25f*acc[1][j] + r0.y;
        o0.z = 0.25f*acc[2][j] + r0.z; o0.w = 0.25f*acc[3][j] + r0.w;
        o1.x = 0.25f*acc[4][j] + r1.x; o1.y = 0.25f*acc[5][j] + r1.y;
        o1.z = 0.25f*acc[6][j] + r1.z; o1.w = 0.25f*acc[7][j] + r1.w;
        *reinterpret_cast<float4*>(out + off)     = o0;
        *reinterpret_cast<float4*>(out + off + 4) = o1;
    }
}

// ---------------- launcher ----------------
extern "C" void kernel_launch(void* const* d_in, const int* in_sizes, int n_in,
                              void* d_out, int out_size) {
    const float* input_l = (const float*)d_in[0];
    const float* input_s = (const float*)d_in[1];
    const float* w_mlb   = (const float*)d_in[2];
    const float* b_mlb   = (const float*)d_in[3];
    const float* a_mlb   = (const float*)d_in[4];
    const float* w_m     = (const float*)d_in[5];
    const float* b_m     = (const float*)d_in[6];
    const float* a_m     = (const float*)d_in[7];
    const float* w_asm   = (const float*)d_in[8];
    const float* b_asm   = (const float*)d_in[9];
    const float* a_asm   = (const float*)d_in[10];
    float* out = (float*)d_out;
    (void)in_sizes; (void)n_in; (void)out_size;

    // 1x1 convs + PReLU
    k_conv_mb  <<<dim3(Pq/256, NB), 256>>>(input_l, w_mlb, b_mlb, a_mlb);
    k_conv_ref <<<dim3(Lk/256, NB), 256>>>(input_s, w_m,   b_m,   a_m);
    k_conv_base<<<dim3(Lk/256, NB), 256>>>(input_s, w_asm, b_asm, a_asm);

    // patch matrices
    k_build_xq<<<(NB*Pq*KQ)/256, 256>>>();
    k_build_wk<<<dim3(Lk, NB), 288>>>();
    k_baseT   <<<(NB*Lk*C64)/256, 256>>>();

    // scores = 10 * Xq @ WkT
    k_sgemm_scores<<<dim3(Lk/128, Pq/128, NB), 256>>>();

    // softmax over keys
    k_softmax<<<dim3(Pq, NB), 256>>>();

    // separable diagonal stencil: probs -> G (result lands back in g_probs)
    k_stencil_w<<<dim3(Lk/256, Pq, NB), 256>>>();
    k_stencil_h<<<dim3(Lk/256, Pq, NB), 256>>>();

    // y = 0.25 * G @ baseT + input_l
    k_sgemm_out<<<dim3(Pq/128, NB), 256>>>(input_l, out);
}

// round 9
// speedup vs baseline: 1.0098x; 1.0098x over previous
#include <cuda_runtime.h>
#include <cstdint>

// ---------------- problem constants ----------------
#define NB   4
#define C64  64
#define CR   32
#define HLq  96
#define WLq  96
#define HSk  48
#define WSk  48
#define Pq   (HLq*WLq)     // 9216 queries
#define Lk   (HSk*WSk)     // 2304 keys
#define KQ   (CR*9)        // 288  (32 ch * 3x3 patch)

// ---------------- device scratch (static, allocation-free) ----------------
__device__ float g_mb   [(size_t)NB*CR*Pq];     // match_base [N,32,96,96]
__device__ float g_ref  [(size_t)NB*CR*Lk];     // ref        [N,32,48,48]
__device__ float g_base [(size_t)NB*C64*Lk];    // base       [N,64,48,48]
__device__ float g_baseT[(size_t)NB*Lk*C64];    // base^T     [N,2304,64]
__device__ float g_xq   [(size_t)NB*Pq*KQ];     // query patches [N,9216,288]
__device__ float g_wkT  [(size_t)NB*KQ*Lk];     // normalized key patches, transposed [N,288,2304]
__device__ float g_probs[(size_t)NB*Pq*Lk];     // scores -> probs -> (after stencil_h) G
__device__ float g_G    [(size_t)NB*Pq*Lk];     // intermediate T (w-pass stencil)

// ---------------- 1x1 conv + PReLU ----------------
template<int CO, int HW>
__device__ __forceinline__ void conv_body(const float* __restrict__ in,
                                          const float* __restrict__ w,
                                          const float* __restrict__ b,
                                          const float* __restrict__ a,
                                          float* __restrict__ out) {
    __shared__ float ws[CO*64];
    __shared__ float bs[CO];
    int tid = threadIdx.x;
    for (int i = tid; i < CO*64; i += 256) ws[i] = w[i];
    for (int i = tid; i < CO;    i += 256) bs[i] = b[i];
    __syncthreads();
    float alpha = __ldg(a);
    int n = blockIdx.y;
    int p = (blockIdx.x << 8) + tid;
    const float* inp = in + (size_t)n*64*HW + p;
    float acc[CO];
#pragma unroll
    for (int co = 0; co < CO; co++) acc[co] = bs[co];
    for (int ci = 0; ci < 64; ci++) {
        float x = inp[(size_t)ci*HW];
#pragma unroll
        for (int co = 0; co < CO; co++) acc[co] = fmaf(ws[co*64+ci], x, acc[co]);
    }
    float* op = out + (size_t)n*CO*HW + p;
#pragma unroll
    for (int co = 0; co < CO; co++) {
        float v = acc[co];
        op[(size_t)co*HW] = v >= 0.f ? v : alpha*v;
    }
}

__global__ __launch_bounds__(256) void k_conv_mb(const float* __restrict__ in,
    const float* __restrict__ w, const float* __restrict__ b, const float* __restrict__ a) {
    conv_body<CR, Pq>(in, w, b, a, g_mb);
}
__global__ __launch_bounds__(256) void k_conv_ref(const float* __restrict__ in,
    const float* __restrict__ w, const float* __restrict__ b, const float* __restrict__ a) {
    conv_body<CR, Lk>(in, w, b, a, g_ref);
}
__global__ __launch_bounds__(256) void k_conv_base(const float* __restrict__ in,
    const float* __restrict__ w, const float* __restrict__ b, const float* __restrict__ a) {
    conv_body<C64, Lk>(in, w, b, a, g_base);
}

// ---------------- build query patch matrix [N, P, 288] ----------------
__global__ __launch_bounds__(256) void k_build_xq() {
    size_t idx = (size_t)blockIdx.x * 256 + threadIdx.x;   // over NB*Pq*KQ (exact grid)
    int k = (int)(idx % KQ);
    size_t t = idx / KQ;
    int p = (int)(t % Pq);
    int n = (int)(t / Pq);
    int c = k / 9, tap = k % 9;
    int h = p / WLq + tap / 3 - 1;
    int w = p % WLq + tap % 3 - 1;
    float v = 0.f;
    if ((unsigned)h < HLq && (unsigned)w < WLq)
        v = g_mb[(((size_t)n*CR + c)*HLq + h)*WLq + w];
    g_xq[idx] = v;
}

// ---------------- build normalized key patches (transposed) [N, 288, L] ----------------
__global__ void k_build_wk() {   // blockDim = 288 (= 9 warps)
    int n = blockIdx.y, l = blockIdx.x;
    int t = threadIdx.x;             // 0..287 : k index c*9 + tap
    int c = t / 9, tap = t % 9;
    int h = l / WSk + tap / 3 - 1;
    int w = l % WSk + tap % 3 - 1;
    float v = 0.f;
    if ((unsigned)h < HSk && (unsigned)w < WSk)
        v = g_ref[(((size_t)n*CR + c)*HSk + h)*WSk + w];
    float s = v*v;
#pragma unroll
    for (int o = 16; o > 0; o >>= 1) s += __shfl_xor_sync(0xffffffffu, s, o);
    __shared__ float part[9];
    __shared__ float nrm;
    if ((t & 31) == 0) part[t >> 5] = s;
    __syncthreads();
    if (t == 0) {
        float tot = 0.f;
#pragma unroll
        for (int i = 0; i < 9; i++) tot += part[i];
        nrm = 1.f / (sqrtf(tot) + 1e-4f);
    }
    __syncthreads();
    g_wkT[((size_t)n*KQ + t)*Lk + l] = v * nrm;
}

// ---------------- transpose base -> [N, L, 64] ----------------
__global__ __launch_bounds__(256) void k_baseT() {
    int idx = (blockIdx.x << 8) + threadIdx.x;     // over NB*Lk*64 (exact)
    int c = idx & 63;
    int t = idx >> 6;
    int l = t % Lk;
    int n = t / Lk;
    g_baseT[idx] = g_base[((size_t)n*C64 + c)*Lk + l];
}

// ---------------- scores GEMM: g_probs = 10 * g_xq @ g_wkT  (per sample) ----------------
// M=9216, N=2304, K=288; 128x128 tile, BK=8, 256 thr, 8x8 microtile
__global__ __launch_bounds__(256) void k_sgemm_scores() {
    __shared__ float As[8][128];
    __shared__ float Bs[8][128];
    const int z = blockIdx.z;
    const float* A = g_xq  + (size_t)z*Pq*KQ;
    const float* B = g_wkT + (size_t)z*KQ*Lk;
    float* Cm      = g_probs + (size_t)z*Pq*Lk;
    const int bm = blockIdx.y << 7;
    const int bn = blockIdx.x << 7;
    const int tid  = threadIdx.x;
    const int arow = tid >> 1, acol = (tid & 1) << 2;
    const int brow = tid >> 5, bcol = (tid & 31) << 2;
    const int ty = tid >> 4,  tx = tid & 15;
    float acc[8][8];
#pragma unroll
    for (int i = 0; i < 8; i++)
#pragma unroll
        for (int j = 0; j < 8; j++) acc[i][j] = 0.f;
    const float* Aptr = A + (size_t)(bm + arow)*KQ + acol;
    const float* Bptr = B + (size_t)brow*Lk + bn + bcol;
    for (int k0 = 0; k0 < KQ; k0 += 8) {
        float4 av = *reinterpret_cast<const float4*>(Aptr + k0);
        float4 bv = *reinterpret_cast<const float4*>(Bptr + (size_t)k0*Lk);
        As[acol+0][arow] = av.x; As[acol+1][arow] = av.y;
        As[acol+2][arow] = av.z; As[acol+3][arow] = av.w;
        *reinterpret_cast<float4*>(&Bs[brow][bcol]) = bv;
        __syncthreads();
#pragma unroll
        for (int kk = 0; kk < 8; kk++) {
            float ar[8], br[8];
            *reinterpret_cast<float4*>(&ar[0]) = *reinterpret_cast<float4*>(&As[kk][ty<<3]);
            *reinterpret_cast<float4*>(&ar[4]) = *reinterpret_cast<float4*>(&As[kk][(ty<<3)+4]);
            *reinterpret_cast<float4*>(&br[0]) = *reinterpret_cast<float4*>(&Bs[kk][tx<<3]);
            *reinterpret_cast<float4*>(&br[4]) = *reinterpret_cast<float4*>(&Bs[kk][(tx<<3)+4]);
#pragma unroll
            for (int i = 0; i < 8; i++)
#pragma unroll
                for (int j = 0; j < 8; j++) acc[i][j] = fmaf(ar[i], br[j], acc[i][j]);
        }
        __syncthreads();
    }
#pragma unroll
    for (int i = 0; i < 8; i++) {
        size_t off = (size_t)(bm + (ty<<3) + i)*Lk + bn + (tx<<3);
        float4 o0, o1;
        o0.x = 10.f*acc[i][0]; o0.y = 10.f*acc[i][1]; o0.z = 10.f*acc[i][2]; o0.w = 10.f*acc[i][3];
        o1.x = 10.f*acc[i][4]; o1.y = 10.f*acc[i][5]; o1.z = 10.f*acc[i][6]; o1.w = 10.f*acc[i][7];
        *reinterpret_cast<float4*>(Cm + off)     = o0;
        *reinterpret_cast<float4*>(Cm + off + 4) = o1;
    }
}

// ---------------- softmax over L=2304 (in place), block per (p, n) ----------------
__global__ __launch_bounds__(256) void k_softmax() {
    int p = blockIdx.x, n = blockIdx.y;
    float* row = g_probs + ((size_t)n*Pq + p) * (size_t)Lk;
    int t = threadIdx.x;
    float v[9];
    float m = -1e30f;
#pragma unroll
    for (int i = 0; i < 9; i++) { v[i] = row[i*256 + t]; m = fmaxf(m, v[i]); }
    __shared__ float red[8];
    __shared__ float bval;
#pragma unroll
    for (int o = 16; o > 0; o >>= 1) m = fmaxf(m, __shfl_xor_sync(0xffffffffu, m, o));
    if ((t & 31) == 0) red[t >> 5] = m;
    __syncthreads();
    if (t == 0) {
        float x = red[0];
#pragma unroll
        for (int i = 1; i < 8; i++) x = fmaxf(x, red[i]);
        bval = x;
    }
    __syncthreads();
    float mm = bval;
    float s = 0.f;
#pragma unroll
    for (int i = 0; i < 9; i++) { v[i] = expf(v[i] - mm); s += v[i]; }
#pragma unroll
    for (int o = 16; o > 0; o >>= 1) s += __shfl_xor_sync(0xffffffffu, s, o);
    if ((t & 31) == 0) red[t >> 5] = s;
    __syncthreads();
    if (t == 0) {
        float x = 0.f;
#pragma unroll
        for (int i = 0; i < 8; i++) x += red[i];
        bval = x;
    }
    __syncthreads();
    float inv = 1.f / bval;
#pragma unroll
    for (int i = 0; i < 9; i++) row[i*256 + t] = v[i] * inv;
}

// ---------------- separable diagonal 9-point stencil ----------------
// G[p',lb] = sum_{dy,dx} probs[p' + 96dy + dx, lb + 48dy + dx] with per-axis bounds.
// w-pass: probs -> g_G ; h-pass: g_G -> probs (reused as G)
__global__ __launch_bounds__(256) void k_stencil_w() {
    int l = (blockIdx.x << 8) + threadIdx.x;
    int p = blockIdx.y, n = blockIdx.z;
    const float* r = g_probs + ((size_t)n*Pq + p) * (size_t)Lk;
    int wq = p % WLq;
    int wb = l % WSk;
    float s = r[l];
    if (wq > 0      && wb > 0)      s += r[(long)l - (Lk + 1)];
    if (wq < WLq-1  && wb < WSk-1)  s += r[(long)l + (Lk + 1)];
    g_G[((size_t)n*Pq + p)*(size_t)Lk + l] = s;
}
__global__ __launch_bounds__(256) void k_stencil_h() {
    int l = (blockIdx.x << 8) + threadIdx.x;
    int p = blockIdx.y, n = blockIdx.z;
    const float* r = g_G + ((size_t)n*Pq + p) * (size_t)Lk;
    int hq = p / WLq;
    int hb = l / WSk;
    const long D = (long)WLq * Lk + WSk;    // 96 rows + 48 cols
    float s = r[l];
    if (hq > 0     && hb > 0)      s += r[(long)l - D];
    if (hq < HLq-1 && hb < HSk-1)  s += r[(long)l + D];
    g_probs[((size_t)n*Pq + p)*(size_t)Lk + l] = s;
}

// ---------------- output GEMM: y = 0.25 * G @ baseT + input_l ----------------
// M=9216, N=64, K=2304; 128x64 tile, BK=16, 256 thr, 8x4 microtile, fused epilogue
__global__ __launch_bounds__(256) void k_sgemm_out(const float* __restrict__ inl,
                                                   float* __restrict__ out) {
    __shared__ float As[16][128];
    __shared__ float Bs[16][64];
    const int n = blockIdx.y;
    const float* A = g_probs + (size_t)n*Pq*Lk;     // G
    const float* B = g_baseT + (size_t)n*Lk*C64;
    const int bm = blockIdx.x << 7;
    const int tid  = threadIdx.x;
    const int arow = tid & 127, acol = (tid >> 7) << 3;   // 0 or 8
    const int brow = tid >> 4,  bcol = (tid & 15) << 2;
    const int ty = tid >> 4, tx = tid & 15;
    float acc[8][4];
#pragma unroll
    for (int i = 0; i < 8; i++)
#pragma unroll
        for (int j = 0; j < 4; j++) acc[i][j] = 0.f;
    const float* Aptr = A + (size_t)(bm + arow)*Lk + acol;
    const float* Bptr = B + (size_t)brow*C64 + bcol;
    for (int k0 = 0; k0 < Lk; k0 += 16) {
        float4 a0 = *reinterpret_cast<const float4*>(Aptr + k0);
        float4 a1 = *reinterpret_cast<const float4*>(Aptr + k0 + 4);
        float4 bv = *reinterpret_cast<const float4*>(Bptr + (size_t)k0*C64);
        As[acol+0][arow] = a0.x; As[acol+1][arow] = a0.y;
        As[acol+2][arow] = a0.z; As[acol+3][arow] = a0.w;
        As[acol+4][arow] = a1.x; As[acol+5][arow] = a1.y;
        As[acol+6][arow] = a1.z; As[acol+7][arow] = a1.w;
        *reinterpret_cast<float4*>(&Bs[brow][bcol]) = bv;
        __syncthreads();
#pragma unroll
        for (int kk = 0; kk < 16; kk++) {
            float ar[8], br[4];
            *reinterpret_cast<float4*>(&ar[0]) = *reinterpret_cast<float4*>(&As[kk][ty<<3]);
            *reinterpret_cast<float4*>(&ar[4]) = *reinterpret_cast<float4*>(&As[kk][(ty<<3)+4]);
            *reinterpret_cast<float4*>(&br[0]) = *reinterpret_cast<float4*>(&Bs[kk][tx<<2]);
#pragma unroll
            for (int i = 0; i < 8; i++)
#pragma unroll
                for (int j = 0; j < 4; j++) acc[i][j] = fmaf(ar[i], br[j], acc[i][j]);
        }
        __syncthreads();
    }
    // epilogue: out[n][c][p] = 0.25*acc + input_l[n][c][p] ; c = tx*4+j, p = bm+ty*8+i
#pragma unroll
    for (int j = 0; j < 4; j++) {
        int c = (tx << 2) + j;
        size_t off = ((size_t)n*C64 + c)*Pq + bm + (ty << 3);
        float4 r0 = *reinterpret_cast<const float4*>(inl + off);
        float4 r1 = *reinterpret_cast<const float4*>(inl + off + 4);
        float4 o0, o1;
        o0.x = 0.25f*acc[0][j] + r0.x; o0.y = 0.25f*acc[1][j] + r0.y;
        o0.z = 0.25f*acc[2][j] + r0.z; o0.w = 0.25f*acc[3][j] + r0.w;
        o1.x = 0.25f*acc[4][j] + r1.x; o1.y = 0.25f*acc[5][j] + r1.y;
        o1.z = 0.25f*acc[6][j] + r1.z; o1.w = 0.25f*acc[7][j] + r1.w;
        *reinterpret_cast<float4*>(out + off)     = o0;
        *reinterpret_cast<float4*>(out + off + 4) = o1;
    }
}

// ---------------- launcher ----------------
extern "C" void kernel_launch(void* const* d_in, const int* in_sizes, int n_in,
                              void* d_out, int out_size) {
    const float* input_l = (const float*)d_in[0];
    const float* input_s = (const float*)d_in[1];
    const float* w_mlb   = (const float*)d_in[2];
    const float* b_mlb   = (const float*)d_in[3];
    const float* a_mlb   = (const float*)d_in[4];
    const float* w_m     = (const float*)d_in[5];
    const float* b_m     = (const float*)d_in[6];
    const float* a_m     = (const float*)d_in[7];
    const float* w_asm   = (const float*)d_in[8];
    const float* b_asm   = (const float*)d_in[9];
    const float* a_asm   = (const float*)d_in[10];
    float* out = (float*)d_out;
    (void)in_sizes; (void)n_in; (void)out_size;

    // 1x1 convs + PReLU
    k_conv_mb  <<<dim3(Pq/256, NB), 256>>>(input_l, w_mlb, b_mlb, a_mlb);
    k_conv_ref <<<dim3(Lk/256, NB), 256>>>(input_s, w_m,   b_m,   a_m);
    k_conv_base<<<dim3(Lk/256, NB), 256>>>(input_s, w_asm, b_asm, a_asm);

    // patch matrices
    k_build_xq<<<(NB*Pq*KQ)/256, 256>>>();
    k_build_wk<<<dim3(Lk, NB), 288>>>();
    k_baseT   <<<(NB*Lk*C64)/256, 256>>>();

    // scores = 10 * Xq @ WkT
    k_sgemm_scores<<<dim3(Lk/128, Pq/128, NB), 256>>>();

    // softmax over keys
    k_softmax<<<dim3(Pq, NB), 256>>>();

    // separable diagonal stencil: probs -> G (result lands back in g_probs)
    k_stencil_w<<<dim3(Lk/256, Pq, NB), 256>>>();
    k_stencil_h<<<dim3(Lk/256, Pq, NB), 256>>>();

    // y = 0.25 * G @ baseT + input_l
    k_sgemm_out<<<dim3(Pq/128, NB), 256>>>(input_l, out);
}